// round 2
// baseline (speedup 1.0000x reference)
#include <cuda_runtime.h>

// Poolpointsinterp: bilinear point sampling from NCHW feature map.
// inputs: d_in[0] = features (8,256,128,128) f32, d_in[1] = rois (P,3) f32
// output: (P,256) f32

#define SPATIAL_SCALE 0.25f
#define Cc 256
#define Hh 128
#define Ww 128

__global__ void __launch_bounds__(Cc) interp_kernel(
    const float* __restrict__ feat,
    const float* __restrict__ rois,
    float* __restrict__ out,
    int P)
{
    int p = blockIdx.x;
    if (p >= P) return;
    int c = threadIdx.x;

    // ROI math: every thread recomputes (broadcast loads, ~free).
    float rb = rois[p * 3 + 0];
    float rx = rois[p * 3 + 1];
    float ry = rois[p * 3 + 2];
    int b = (int)rb;
    float x = rx * SPATIAL_SCALE;
    float y = ry * SPATIAL_SCALE;

    bool valid = (y >= -1.0f) & (y <= (float)Hh) & (x >= -1.0f) & (x <= (float)Ww);

    y = fmaxf(y, 0.0f);
    x = fmaxf(x, 0.0f);
    int y_low = (int)floorf(y);
    int x_low = (int)floorf(x);
    int y_high, x_high;
    if (y_low >= Hh - 1) { y_low = Hh - 1; y_high = Hh - 1; y = (float)y_low; }
    else                 { y_high = y_low + 1; }
    if (x_low >= Ww - 1) { x_low = Ww - 1; x_high = Ww - 1; x = (float)x_low; }
    else                 { x_high = x_low + 1; }

    float ly = y - (float)y_low;
    float lx = x - (float)x_low;
    float hy = 1.0f - ly;
    float hx = 1.0f - lx;
    float w1 = hy * hx, w2 = hy * lx, w3 = ly * hx, w4 = ly * lx;

    const float* fb = feat + ((size_t)b * Cc + c) * (Hh * Ww);
    int o_lo = y_low * Ww;
    int o_hi = y_high * Ww;
    float v1 = fb[o_lo + x_low];
    float v2 = fb[o_lo + x_high];
    float v3 = fb[o_hi + x_low];
    float v4 = fb[o_hi + x_high];

    float o = w1 * v1 + w2 * v2 + w3 * v3 + w4 * v4;
    out[(size_t)p * Cc + c] = valid ? o : 0.0f;
}

extern "C" void kernel_launch(void* const* d_in, const int* in_sizes, int n_in,
                              void* d_out, int out_size)
{
    const float* feat = (const float*)d_in[0];
    const float* rois = (const float*)d_in[1];
    float* out = (float*)d_out;
    int P = in_sizes[1] / 3;

    interp_kernel<<<P, Cc>>>(feat, rois, out, P);
}

// round 3
// speedup vs baseline: 4.0590x; 4.0590x over previous
#include <cuda_runtime.h>

// Poolpointsinterp: bilinear point sampling.
// Strategy: NCHW -> NHWC transpose into __device__ scratch (fully coalesced
// both passes), then per-point gather of 4 contiguous 1KB channel vectors.

#define SPATIAL_SCALE 0.25f
#define Nn 8
#define Cc 256
#define Hh 128
#define Ww 128

// 8*256*128*128 floats = 128 MB scratch in NHWC layout: [((b*H+y)*W+x)*C + c]
__device__ float g_nhwc[(size_t)Nn * Hh * Ww * Cc];

// ---------------------------------------------------------------------------
// Kernel 1: NCHW -> NHWC transpose, 32(c) x 32(x) shared tiles.
// grid = (W/32, C/32, N*H), block = (32, 8)
// ---------------------------------------------------------------------------
__global__ void __launch_bounds__(256) transpose_kernel(const float* __restrict__ feat)
{
    __shared__ float tile[32][33];

    int xb = blockIdx.x * 32;          // x tile origin
    int cb = blockIdx.y * 32;          // c tile origin
    int bh = blockIdx.z;               // b*H + y
    int b  = bh / Hh;
    int y  = bh % Hh;
    int tx = threadIdx.x;              // 0..31
    int ty = threadIdx.y;              // 0..7

    // Read: coalesced along x. feat[((b*C + c)*H + y)*W + x]
    const float* src = feat + (((size_t)b * Cc + cb) * Hh + y) * Ww + xb;
    #pragma unroll
    for (int j = 0; j < 32; j += 8) {
        tile[ty + j][tx] = src[(size_t)(ty + j) * (Hh * Ww) + tx];
    }
    __syncthreads();

    // Write: coalesced along c. g_nhwc[((b*H+y)*W + x)*C + c]
    float* dst = g_nhwc + ((size_t)bh * Ww + xb) * Cc + cb;
    #pragma unroll
    for (int j = 0; j < 32; j += 8) {
        dst[(size_t)(ty + j) * Cc + tx] = tile[tx][ty + j];
    }
}

// ---------------------------------------------------------------------------
// Kernel 2: per-point gather. 64 threads per point, float4 per thread.
// block = 128 threads -> 2 points per block.
// ---------------------------------------------------------------------------
__global__ void __launch_bounds__(128) gather_kernel(
    const float* __restrict__ rois,
    float* __restrict__ out,
    int P)
{
    int p = blockIdx.x * 2 + (threadIdx.x >> 6);
    if (p >= P) return;
    int t = threadIdx.x & 63;          // 0..63, channel group (4 channels each)

    float rb = rois[p * 3 + 0];
    float rx = rois[p * 3 + 1];
    float ry = rois[p * 3 + 2];
    int b = (int)rb;
    float x = rx * SPATIAL_SCALE;
    float y = ry * SPATIAL_SCALE;

    bool valid = (y >= -1.0f) & (y <= (float)Hh) & (x >= -1.0f) & (x <= (float)Ww);

    y = fmaxf(y, 0.0f);
    x = fmaxf(x, 0.0f);
    int y_low = (int)floorf(y);
    int x_low = (int)floorf(x);
    int y_high, x_high;
    if (y_low >= Hh - 1) { y_low = Hh - 1; y_high = Hh - 1; y = (float)y_low; }
    else                 { y_high = y_low + 1; }
    if (x_low >= Ww - 1) { x_low = Ww - 1; x_high = Ww - 1; x = (float)x_low; }
    else                 { x_high = x_low + 1; }

    float ly = y - (float)y_low;
    float lx = x - (float)x_low;
    float hy = 1.0f - ly;
    float hx = 1.0f - lx;
    float w1 = hy * hx, w2 = hy * lx, w3 = ly * hx, w4 = ly * lx;

    size_t base = (size_t)b * Hh * Ww;
    const float4* p1 = (const float4*)(g_nhwc + ((base + (size_t)y_low  * Ww + x_low ) * Cc)) + t;
    const float4* p2 = (const float4*)(g_nhwc + ((base + (size_t)y_low  * Ww + x_high) * Cc)) + t;
    const float4* p3 = (const float4*)(g_nhwc + ((base + (size_t)y_high * Ww + x_low ) * Cc)) + t;
    const float4* p4 = (const float4*)(g_nhwc + ((base + (size_t)y_high * Ww + x_high) * Cc)) + t;

    float4 v1 = *p1;
    float4 v2 = *p2;
    float4 v3 = *p3;
    float4 v4 = *p4;

    float4 o;
    o.x = w1 * v1.x + w2 * v2.x + w3 * v3.x + w4 * v4.x;
    o.y = w1 * v1.y + w2 * v2.y + w3 * v3.y + w4 * v4.y;
    o.z = w1 * v1.z + w2 * v2.z + w3 * v3.z + w4 * v4.z;
    o.w = w1 * v1.w + w2 * v2.w + w3 * v3.w + w4 * v4.w;

    if (!valid) { o.x = 0.0f; o.y = 0.0f; o.z = 0.0f; o.w = 0.0f; }

    ((float4*)(out + (size_t)p * Cc))[t] = o;
}

extern "C" void kernel_launch(void* const* d_in, const int* in_sizes, int n_in,
                              void* d_out, int out_size)
{
    const float* feat = (const float*)d_in[0];
    const float* rois = (const float*)d_in[1];
    float* out = (float*)d_out;
    int P = in_sizes[1] / 3;

    dim3 tgrid(Ww / 32, Cc / 32, Nn * Hh);
    dim3 tblock(32, 8);
    transpose_kernel<<<tgrid, tblock>>>(feat);

    gather_kernel<<<(P + 1) / 2, 128>>>(rois, out, P);
}

// round 4
// speedup vs baseline: 4.2966x; 1.0585x over previous
#include <cuda_runtime.h>
#include <cuda_fp16.h>

// Poolpointsinterp: bilinear point sampling.
// NCHW fp32 -> NHWC fp16 scratch (64 MB, L2-resident) -> per-point gather.

#define SPATIAL_SCALE 0.25f
#define Nn 8
#define Cc 256
#define Hh 128
#define Ww 128

// 8*128*128*256 halves = 64 MB, NHWC: [((b*H+y)*W+x)*C + c]
__device__ __half g_nhwc[(size_t)Nn * Hh * Ww * Cc];

// ---------------------------------------------------------------------------
// Kernel 1: NCHW fp32 -> NHWC fp16 transpose. 32(c) x 32(x) tiles.
// grid = (W/32, C/32, N*H), block = (32, 8)
// ---------------------------------------------------------------------------
__global__ void __launch_bounds__(256) transpose_kernel(const float* __restrict__ feat)
{
    __shared__ float tile[32][33];   // [c_local][x_local]

    int xb = blockIdx.x * 32;
    int cb = blockIdx.y * 32;
    int bh = blockIdx.z;             // b*H + y
    int b  = bh / Hh;
    int y  = bh % Hh;
    int tx = threadIdx.x;            // 0..31
    int ty = threadIdx.y;            // 0..7

    // Read: coalesced along x.
    const float* src = feat + (((size_t)b * Cc + cb) * Hh + y) * Ww + xb;
    #pragma unroll
    for (int j = 0; j < 32; j += 8) {
        tile[ty + j][tx] = src[(size_t)(ty + j) * (Hh * Ww) + tx];
    }
    __syncthreads();

    // Write: coalesced along c, packed as half2. 512 half2 per block, 2/thread.
    int tid = ty * 32 + tx;
    __half* dstbase = g_nhwc + ((size_t)bh * Ww + xb) * Cc + cb;
    #pragma unroll
    for (int i = 0; i < 2; i++) {
        int idx = i * 256 + tid;
        int x   = idx >> 4;          // 0..31
        int c2  = idx & 15;          // 0..15 (half2 index)
        __half2 v = __floats2half2_rn(tile[2 * c2][x], tile[2 * c2 + 1][x]);
        *(__half2*)(dstbase + (size_t)x * Cc + 2 * c2) = v;
    }
}

// ---------------------------------------------------------------------------
// Kernel 2: gather. One warp per point; lane t covers channels 8t..8t+7.
// Each corner read = 512 B contiguous (32 lanes x uint4 of 8 halves).
// block = 256 threads -> 8 points/block.
// ---------------------------------------------------------------------------
__global__ void __launch_bounds__(256) gather_kernel(
    const float* __restrict__ rois,
    float* __restrict__ out,
    int P)
{
    int p = blockIdx.x * 8 + (threadIdx.x >> 5);
    if (p >= P) return;
    int t = threadIdx.x & 31;

    float rb = rois[p * 3 + 0];
    float rx = rois[p * 3 + 1];
    float ry = rois[p * 3 + 2];
    int bi = (int)rb;
    float x = rx * SPATIAL_SCALE;
    float y = ry * SPATIAL_SCALE;

    bool valid = (y >= -1.0f) & (y <= (float)Hh) & (x >= -1.0f) & (x <= (float)Ww);

    y = fmaxf(y, 0.0f);
    x = fmaxf(x, 0.0f);
    int y_low = (int)floorf(y);
    int x_low = (int)floorf(x);
    int y_high, x_high;
    if (y_low >= Hh - 1) { y_low = Hh - 1; y_high = Hh - 1; y = (float)y_low; }
    else                 { y_high = y_low + 1; }
    if (x_low >= Ww - 1) { x_low = Ww - 1; x_high = Ww - 1; x = (float)x_low; }
    else                 { x_high = x_low + 1; }

    float ly = y - (float)y_low;
    float lx = x - (float)x_low;
    float hy = 1.0f - ly;
    float hx = 1.0f - lx;
    float w1 = hy * hx, w2 = hy * lx, w3 = ly * hx, w4 = ly * lx;

    size_t base = (size_t)bi * Hh * Ww;
    const uint4* q1 = ((const uint4*)(g_nhwc + (base + (size_t)y_low  * Ww + x_low ) * Cc)) + t;
    const uint4* q2 = ((const uint4*)(g_nhwc + (base + (size_t)y_low  * Ww + x_high) * Cc)) + t;
    const uint4* q3 = ((const uint4*)(g_nhwc + (base + (size_t)y_high * Ww + x_low ) * Cc)) + t;
    const uint4* q4 = ((const uint4*)(g_nhwc + (base + (size_t)y_high * Ww + x_high) * Cc)) + t;

    uint4 a = *q1, b4 = *q2, c4 = *q3, d4 = *q4;
    const __half2* ah = (const __half2*)&a;
    const __half2* bh2 = (const __half2*)&b4;
    const __half2* ch = (const __half2*)&c4;
    const __half2* dh = (const __half2*)&d4;

    float o[8];
    #pragma unroll
    for (int i = 0; i < 4; i++) {
        float2 f1 = __half22float2(ah[i]);
        float2 f2 = __half22float2(bh2[i]);
        float2 f3 = __half22float2(ch[i]);
        float2 f4 = __half22float2(dh[i]);
        o[2 * i + 0] = w1 * f1.x + w2 * f2.x + w3 * f3.x + w4 * f4.x;
        o[2 * i + 1] = w1 * f1.y + w2 * f2.y + w3 * f3.y + w4 * f4.y;
    }

    if (!valid) {
        #pragma unroll
        for (int i = 0; i < 8; i++) o[i] = 0.0f;
    }

    float4* dst = (float4*)(out + (size_t)p * Cc + t * 8);
    dst[0] = make_float4(o[0], o[1], o[2], o[3]);
    dst[1] = make_float4(o[4], o[5], o[6], o[7]);
}

extern "C" void kernel_launch(void* const* d_in, const int* in_sizes, int n_in,
                              void* d_out, int out_size)
{
    const float* feat = (const float*)d_in[0];
    const float* rois = (const float*)d_in[1];
    float* out = (float*)d_out;
    int P = in_sizes[1] / 3;

    dim3 tgrid(Ww / 32, Cc / 32, Nn * Hh);
    dim3 tblock(32, 8);
    transpose_kernel<<<tgrid, tblock>>>(feat);

    gather_kernel<<<(P + 7) / 8, 256>>>(rois, out, P);
}

// round 6
// speedup vs baseline: 4.7909x; 1.1150x over previous
#include <cuda_runtime.h>
#include <cuda_fp16.h>

// Poolpointsinterp: bilinear point sampling.
// NCHW fp32 -> NHWC fp16 scratch (64 MB, L2-resident) -> per-point gather.

#define SPATIAL_SCALE 0.25f
#define Nn 8
#define Cc 256
#define Hh 128
#define Ww 128

// 8*128*128*256 halves = 64 MB, NHWC: [((b*H+y)*W+x)*C + c]
__device__ __half g_nhwc[(size_t)Nn * Hh * Ww * Cc];

// ---------------------------------------------------------------------------
// Kernel 1: NCHW fp32 -> NHWC fp16 transpose.
// Tile: 32 channels x 128 x (one full row of one (b,y)).
// grid = (C/32, N*H), block = 256.
// ---------------------------------------------------------------------------
__global__ void __launch_bounds__(256) transpose_kernel(const float* __restrict__ feat)
{
    __shared__ float tile[32][129];   // odd pad: scalar-STS/LDS conflict-free

    int cb = blockIdx.x * 32;
    int bh = blockIdx.y;              // b*H + y
    int b  = bh / Hh;
    int y  = bh % Hh;
    int tid = threadIdx.x;

    // ---- Load: 32 rows x 128 floats. Thread (c = tid/8, xq = tid%8) loads
    // 4 float4's (LDG.128, warp covers 512B contiguous per row segment),
    // then stores them as 4 scalar STS each (16B-alignment-safe, bank-clean).
    int c  = tid >> 3;
    int xq = tid & 7;
    const float4* src = (const float4*)(feat + (((size_t)b * Cc + cb + c) * Hh + y) * Ww);
    #pragma unroll
    for (int i = 0; i < 4; i++) {
        int f4 = i * 8 + xq;
        float4 v = src[f4];
        tile[c][f4 * 4 + 0] = v.x;
        tile[c][f4 * 4 + 1] = v.y;
        tile[c][f4 * 4 + 2] = v.z;
        tile[c][f4 * 4 + 3] = v.w;
    }
    __syncthreads();

    // ---- Write: for each x, 32 channels = 64B, emitted as 8B uint2 chunks
    // (4 channels each). 1024 uint2 per block, 4 per thread.
    __half* dstbase = g_nhwc + (size_t)bh * Ww * Cc + cb;
    #pragma unroll
    for (int it = 0; it < 4; it++) {
        int idx = it * 256 + tid;
        int x = idx >> 3;             // 0..127
        int j = idx & 7;              // channel quad: local channels 4j..4j+3
        __half2 lo = __floats2half2_rn(tile[4 * j + 0][x], tile[4 * j + 1][x]);
        __half2 hi = __floats2half2_rn(tile[4 * j + 2][x], tile[4 * j + 3][x]);
        uint2 pack;
        pack.x = *(const unsigned*)&lo;
        pack.y = *(const unsigned*)&hi;
        *(uint2*)(dstbase + (size_t)x * Cc + 4 * j) = pack;
    }
}

// ---------------------------------------------------------------------------
// Kernel 2: gather. One warp per point; lane t covers channels 8t..8t+7.
// Each corner read = 512 B contiguous. block = 256 -> 8 points/block.
// ---------------------------------------------------------------------------
__global__ void __launch_bounds__(256) gather_kernel(
    const float* __restrict__ rois,
    float* __restrict__ out,
    int P)
{
    int p = blockIdx.x * 8 + (threadIdx.x >> 5);
    if (p >= P) return;
    int t = threadIdx.x & 31;

    float rb = rois[p * 3 + 0];
    float rx = rois[p * 3 + 1];
    float ry = rois[p * 3 + 2];
    int bi = (int)rb;
    float x = rx * SPATIAL_SCALE;
    float y = ry * SPATIAL_SCALE;

    bool valid = (y >= -1.0f) & (y <= (float)Hh) & (x >= -1.0f) & (x <= (float)Ww);

    y = fmaxf(y, 0.0f);
    x = fmaxf(x, 0.0f);
    int y_low = (int)floorf(y);
    int x_low = (int)floorf(x);
    int dxs = 1, dys = 1;
    if (y_low >= Hh - 1) { y_low = Hh - 1; dys = 0; y = (float)y_low; }
    if (x_low >= Ww - 1) { x_low = Ww - 1; dxs = 0; x = (float)x_low; }

    float ly = y - (float)y_low;
    float lx = x - (float)x_low;
    float hy = 1.0f - ly;
    float hx = 1.0f - lx;
    float w1 = hy * hx, w2 = hy * lx, w3 = ly * hx, w4 = ly * lx;

    // One base pointer, integer deltas in uint4 units (pixel = 512B = 32 uint4).
    const uint4* q1 = ((const uint4*)g_nhwc)
                    + ((size_t)(bi * Hh + y_low) * Ww + x_low) * 32 + t;
    int dx = dxs * 32;
    int dy = dys * (Ww * 32);

    uint4 a  = q1[0];
    uint4 b4 = q1[dx];
    uint4 c4 = q1[dy];
    uint4 d4 = q1[dy + dx];

    const __half2* ah  = (const __half2*)&a;
    const __half2* bh2 = (const __half2*)&b4;
    const __half2* ch  = (const __half2*)&c4;
    const __half2* dh  = (const __half2*)&d4;

    float o[8];
    #pragma unroll
    for (int i = 0; i < 4; i++) {
        float2 f1 = __half22float2(ah[i]);
        float2 f2 = __half22float2(bh2[i]);
        float2 f3 = __half22float2(ch[i]);
        float2 f4 = __half22float2(dh[i]);
        o[2 * i + 0] = w1 * f1.x + w2 * f2.x + w3 * f3.x + w4 * f4.x;
        o[2 * i + 1] = w1 * f1.y + w2 * f2.y + w3 * f3.y + w4 * f4.y;
    }

    if (!valid) {
        #pragma unroll
        for (int i = 0; i < 8; i++) o[i] = 0.0f;
    }

    float4* dst = (float4*)(out + (size_t)p * Cc + t * 8);
    dst[0] = make_float4(o[0], o[1], o[2], o[3]);
    dst[1] = make_float4(o[4], o[5], o[6], o[7]);
}

extern "C" void kernel_launch(void* const* d_in, const int* in_sizes, int n_in,
                              void* d_out, int out_size)
{
    const float* feat = (const float*)d_in[0];
    const float* rois = (const float*)d_in[1];
    float* out = (float*)d_out;
    int P = in_sizes[1] / 3;

    dim3 tgrid(Cc / 32, Nn * Hh);
    transpose_kernel<<<tgrid, 256>>>(feat);

    gather_kernel<<<(P + 7) / 8, 256>>>(rois, out, P);
}

// round 7
// speedup vs baseline: 6.5423x; 1.3656x over previous
#include <cuda_runtime.h>
#include <cuda_fp16.h>

// Poolpointsinterp: bilinear point sampling.
// NCHW fp32 -> NHWC fp16 scratch (64 MB, L2-resident) -> per-point gather.
// R7: 2 points/warp (MLP 8), streaming hints to protect scratch in L2.

#define SPATIAL_SCALE 0.25f
#define Nn 8
#define Cc 256
#define Hh 128
#define Ww 128

// 8*128*128*256 halves = 64 MB, NHWC: [((b*H+y)*W+x)*C + c]
__device__ __half g_nhwc[(size_t)Nn * Hh * Ww * Cc];

// ---------------------------------------------------------------------------
// Kernel 1: NCHW fp32 -> NHWC fp16 transpose.
// grid = (C/32, N*H), block = 256.
// ---------------------------------------------------------------------------
__global__ void __launch_bounds__(256) transpose_kernel(const float* __restrict__ feat)
{
    __shared__ float tile[32][129];   // odd pad: scalar-STS/LDS conflict-free

    int cb = blockIdx.x * 32;
    int bh = blockIdx.y;              // b*H + y
    int b  = bh / Hh;
    int y  = bh % Hh;
    int tid = threadIdx.x;

    // Load: thread (c = tid/8, xq = tid%8) reads 4 float4 (evict-first: feat
    // is touched exactly once; keep L2 for the scratch).
    int c  = tid >> 3;
    int xq = tid & 7;
    const float4* src = (const float4*)(feat + (((size_t)b * Cc + cb + c) * Hh + y) * Ww);
    #pragma unroll
    for (int i = 0; i < 4; i++) {
        int f4 = i * 8 + xq;
        float4 v = __ldcs(src + f4);
        tile[c][f4 * 4 + 0] = v.x;
        tile[c][f4 * 4 + 1] = v.y;
        tile[c][f4 * 4 + 2] = v.z;
        tile[c][f4 * 4 + 3] = v.w;
    }
    __syncthreads();

    // Write: for each x, 32 channels = 64B as 8B uint2 chunks. Plain stores:
    // scratch WANTS to live in L2 (gather reads it in this same launch).
    __half* dstbase = g_nhwc + (size_t)bh * Ww * Cc + cb;
    #pragma unroll
    for (int it = 0; it < 4; it++) {
        int idx = it * 256 + tid;
        int x = idx >> 3;
        int j = idx & 7;
        __half2 lo = __floats2half2_rn(tile[4 * j + 0][x], tile[4 * j + 1][x]);
        __half2 hi = __floats2half2_rn(tile[4 * j + 2][x], tile[4 * j + 3][x]);
        uint2 pack;
        pack.x = *(const unsigned*)&lo;
        pack.y = *(const unsigned*)&hi;
        *(uint2*)(dstbase + (size_t)x * Cc + 4 * j) = pack;
    }
}

// ---------------------------------------------------------------------------
// ROI math helper: returns base uint4 index + deltas + weights for one point.
// ---------------------------------------------------------------------------
struct PointAddr {
    size_t base;   // uint4 index of corner (y_low, x_low)
    int dx, dy;    // uint4 deltas to the high corners
    float w1, w2, w3, w4;
    bool valid;
};

__device__ __forceinline__ PointAddr roi_math(const float* __restrict__ rois, int p)
{
    PointAddr r;
    float rb = rois[p * 3 + 0];
    float rx = rois[p * 3 + 1];
    float ry = rois[p * 3 + 2];
    int bi = (int)rb;
    float x = rx * SPATIAL_SCALE;
    float y = ry * SPATIAL_SCALE;

    r.valid = (y >= -1.0f) & (y <= (float)Hh) & (x >= -1.0f) & (x <= (float)Ww);

    y = fmaxf(y, 0.0f);
    x = fmaxf(x, 0.0f);
    int y_low = (int)floorf(y);
    int x_low = (int)floorf(x);
    int dxs = 1, dys = 1;
    if (y_low >= Hh - 1) { y_low = Hh - 1; dys = 0; y = (float)y_low; }
    if (x_low >= Ww - 1) { x_low = Ww - 1; dxs = 0; x = (float)x_low; }

    float ly = y - (float)y_low;
    float lx = x - (float)x_low;
    float hy = 1.0f - ly;
    float hx = 1.0f - lx;
    r.w1 = hy * hx; r.w2 = hy * lx; r.w3 = ly * hx; r.w4 = ly * lx;

    r.base = ((size_t)(bi * Hh + y_low) * Ww + x_low) * 32;
    r.dx = dxs * 32;
    r.dy = dys * (Ww * 32);
    return r;
}

__device__ __forceinline__ void blend_store(
    const uint4& a, const uint4& b4, const uint4& c4, const uint4& d4,
    const PointAddr& r, float* __restrict__ out, int p, int t)
{
    const __half2* ah  = (const __half2*)&a;
    const __half2* bh2 = (const __half2*)&b4;
    const __half2* ch  = (const __half2*)&c4;
    const __half2* dh  = (const __half2*)&d4;

    float o[8];
    #pragma unroll
    for (int i = 0; i < 4; i++) {
        float2 f1 = __half22float2(ah[i]);
        float2 f2 = __half22float2(bh2[i]);
        float2 f3 = __half22float2(ch[i]);
        float2 f4 = __half22float2(dh[i]);
        o[2 * i + 0] = r.w1 * f1.x + r.w2 * f2.x + r.w3 * f3.x + r.w4 * f4.x;
        o[2 * i + 1] = r.w1 * f1.y + r.w2 * f2.y + r.w3 * f3.y + r.w4 * f4.y;
    }
    if (!r.valid) {
        #pragma unroll
        for (int i = 0; i < 8; i++) o[i] = 0.0f;
    }
    // Streaming stores: out is never re-read; don't evict scratch from L2.
    float4* dst = (float4*)(out + (size_t)p * Cc + t * 8);
    __stcs(dst + 0, make_float4(o[0], o[1], o[2], o[3]));
    __stcs(dst + 1, make_float4(o[4], o[5], o[6], o[7]));
}

// ---------------------------------------------------------------------------
// Kernel 2: gather. One warp per 2 points; all 8 corner loads issued
// back-to-back (MLP=8) before any blending. block = 256 -> 16 points/block.
// ---------------------------------------------------------------------------
__global__ void __launch_bounds__(256) gather_kernel(
    const float* __restrict__ rois,
    float* __restrict__ out,
    int P)
{
    int w = blockIdx.x * 8 + (threadIdx.x >> 5);
    int p0 = w * 2;
    int p1 = p0 + 1;
    if (p0 >= P) return;
    int t = threadIdx.x & 31;

    bool has1 = (p1 < P);
    PointAddr r0 = roi_math(rois, p0);
    PointAddr r1 = roi_math(rois, has1 ? p1 : p0);

    const uint4* g = (const uint4*)g_nhwc;
    const uint4* q0 = g + r0.base + t;
    const uint4* q1 = g + r1.base + t;

    // Batch-issue all 8 independent loads.
    uint4 a0 = q0[0];
    uint4 b0 = q0[r0.dx];
    uint4 c0 = q0[r0.dy];
    uint4 d0 = q0[r0.dy + r0.dx];
    uint4 a1 = q1[0];
    uint4 b1 = q1[r1.dx];
    uint4 c1 = q1[r1.dy];
    uint4 d1 = q1[r1.dy + r1.dx];

    blend_store(a0, b0, c0, d0, r0, out, p0, t);
    if (has1)
        blend_store(a1, b1, c1, d1, r1, out, p1, t);
}

extern "C" void kernel_launch(void* const* d_in, const int* in_sizes, int n_in,
                              void* d_out, int out_size)
{
    const float* feat = (const float*)d_in[0];
    const float* rois = (const float*)d_in[1];
    float* out = (float*)d_out;
    int P = in_sizes[1] / 3;

    dim3 tgrid(Cc / 32, Nn * Hh);
    transpose_kernel<<<tgrid, 256>>>(feat);

    int pts_per_block = 16;
    gather_kernel<<<(P + pts_per_block - 1) / pts_per_block, 256>>>(rois, out, P);
}